// round 6
// baseline (speedup 1.0000x reference)
#include <cuda_runtime.h>
#include <cuda_bf16.h>

// ---------------------------------------------------------------------------
// MHCLayerAITER fused single-kernel, low-register variant.
// out[b,i,c] = sum_j M[i][j]*x[b,j,c] + 2*sig(H_post[i]) * y[b,c]
//   y[b,c]   = bf16(x_agg[b,c]) / rms_b * bf16(w[c])
//   x_agg    = sum_n sig(H_pre[n]) * x[b,n,c]
//   rms_b    = sqrt(mean_c bf16(x_agg)^2 + 1e-6)
//   M        = sinkhorn_knopp(exp(H_res), 3 iters, eps=1e-6)
// B=8192, n=4, C=2048. HBM-bound: 268MB in + 268MB out.
//
// Key structure vs previous round:
//  - Sinkhorn (warp 0, shuffle butterflies) runs BEFORE the x loads with a
//    barrier in between, so its temporaries never overlap the x registers.
//  - 512 threads/CTA, one float4 column per thread: x register tile is 16
//    regs instead of 32 -> higher occupancy, better DRAM latency hiding.
//  - M / hpost read from smem row-at-a-time in the epilogue (5 live regs,
//    not 24 held across the whole kernel).
//  - __ldcs/__stcs streaming hints on the 512MB x/out stream.
// ---------------------------------------------------------------------------

namespace {
constexpr int kB = 8192;
constexpr int kN = 4;
constexpr int kC = 2048;
constexpr int kThreads = 512;
constexpr int kC4 = kC / 4;            // 512 float4 per stream per row (== kThreads)
constexpr float kEps = 1e-6f;
}

__global__ __launch_bounds__(kThreads) void mhc_fused_kernel(
    const float4* __restrict__ x,      // [B, n, C/4]
    const float4* __restrict__ w,      // [C/4]
    const float*  __restrict__ H_pre,  // [4]
    const float*  __restrict__ H_post, // [4]
    const float*  __restrict__ H_res,  // [4,4]
    float4* __restrict__ out) {        // [B, n, C/4]
    const int b = blockIdx.x;
    const int t = threadIdx.x;

    __shared__ float s_params[24];     // M[16] | sig(H_pre)[4] | 2*sig(H_post)[4]
    __shared__ float s_warp[kThreads / 32];
    __shared__ float s_rinv;

    // ---- Phase 0 (warp 0): Sinkhorn-Knopp on exp(H_res) + activations.
    // Lane l (<16) owns P[l/4][l%4]. Row sums via butterfly offsets {1,2},
    // column sums via {4,8}. Lanes 16-31 run with p=1; their butterflies stay
    // in the upper half. Temporaries die at the barrier below, so this adds
    // no register pressure to the streaming phase.
    if (t < 32) {
        const int lane = t;
        float h = (lane < 16) ? H_res[lane] : 0.0f;
        float p = expf(h);
#pragma unroll
        for (int it = 0; it < 3; ++it) {
            float s = p;
            s += __shfl_xor_sync(0xFFFFFFFFu, s, 1);
            s += __shfl_xor_sync(0xFFFFFFFFu, s, 2);
            p = p / (s + kEps);          // row normalize
            s = p;
            s += __shfl_xor_sync(0xFFFFFFFFu, s, 4);
            s += __shfl_xor_sync(0xFFFFFFFFu, s, 8);
            p = p / (s + kEps);          // column normalize
        }
        if (lane < 16) {
            s_params[lane] = p;
        } else if (lane < 20) {
            s_params[lane] = 1.0f / (1.0f + expf(-H_pre[lane - 16]));
        } else if (lane < 24) {
            s_params[lane] = 2.0f / (1.0f + expf(-H_post[lane - 20]));
        }
    }
    __syncthreads();

    // ---- Phase 1: stream x (read once, streaming hint), aggregate ----------
    const size_t base = (size_t)b * (kN * kC4) + t;   // this thread's column

    float4 xr[kN];
#pragma unroll
    for (int n = 0; n < kN; ++n)
        xr[n] = __ldcs(&x[base + (size_t)n * kC4]);

    float hp0 = s_params[16], hp1 = s_params[17];
    float hp2 = s_params[18], hp3 = s_params[19];

    float aggb[4];
    float lsum = 0.0f;
#pragma unroll
    for (int q = 0; q < 4; ++q) {
        const float* e0 = &xr[0].x;
        const float* e1 = &xr[1].x;
        const float* e2 = &xr[2].x;
        const float* e3 = &xr[3].x;
        float a = hp0 * e0[q];
        a = fmaf(hp1, e1[q], a);
        a = fmaf(hp2, e2[q], a);
        a = fmaf(hp3, e3[q], a);
        float ab = __bfloat162float(__float2bfloat16_rn(a));
        aggb[q] = ab;
        lsum = fmaf(ab, ab, lsum);
    }

    // ---- Phase 2: block reduction of sum of squares over C=2048 ------------
#pragma unroll
    for (int off = 16; off > 0; off >>= 1)
        lsum += __shfl_xor_sync(0xFFFFFFFFu, lsum, off);

    const int wid = t >> 5;
    const int lane = t & 31;
    if (lane == 0) s_warp[wid] = lsum;
    __syncthreads();
    if (t == 0) {
        float s = 0.0f;
#pragma unroll
        for (int i = 0; i < kThreads / 32; ++i) s += s_warp[i];
        float rms = sqrtf(s * (1.0f / (float)kC) + kEps);
        s_rinv = 1.0f / rms;
    }
    __syncthreads();
    const float rinv = s_rinv;

    // ---- Phase 3: y_norm (w is L1/L2-resident, default caching) ------------
    float4 wv = w[t];
    float y[4];
    y[0] = aggb[0] * rinv * __bfloat162float(__float2bfloat16_rn(wv.x));
    y[1] = aggb[1] * rinv * __bfloat162float(__float2bfloat16_rn(wv.y));
    y[2] = aggb[2] * rinv * __bfloat162float(__float2bfloat16_rn(wv.z));
    y[3] = aggb[3] * rinv * __bfloat162float(__float2bfloat16_rn(wv.w));

    // ---- Phase 4: mix + combine, streaming stores ---------------------------
#pragma unroll
    for (int i = 0; i < kN; ++i) {
        // Read one M row + hpost[i] from smem (uniform broadcast, cheap).
        const float m0 = s_params[i * 4 + 0];
        const float m1 = s_params[i * 4 + 1];
        const float m2 = s_params[i * 4 + 2];
        const float m3 = s_params[i * 4 + 3];
        const float hpost_i = s_params[20 + i];

        float4 o;
        const float* e0 = &xr[0].x;
        const float* e1 = &xr[1].x;
        const float* e2 = &xr[2].x;
        const float* e3 = &xr[3].x;
        float r[4];
#pragma unroll
        for (int q = 0; q < 4; ++q) {
            float acc = hpost_i * y[q];
            acc = fmaf(m0, e0[q], acc);
            acc = fmaf(m1, e1[q], acc);
            acc = fmaf(m2, e2[q], acc);
            acc = fmaf(m3, e3[q], acc);
            r[q] = acc;
        }
        o.x = r[0]; o.y = r[1]; o.z = r[2]; o.w = r[3];
        __stcs(&out[base + (size_t)i * kC4], o);
    }
}

// ---------------------------------------------------------------------------
// Launch. Inputs (metadata order): x, rmsnorm_weight, H_pre, H_post, H_res.
// Single graph node.
// ---------------------------------------------------------------------------
extern "C" void kernel_launch(void* const* d_in, const int* in_sizes, int n_in,
                              void* d_out, int out_size) {
    const float* x      = (const float*)d_in[0];
    const float* w      = (const float*)d_in[1];
    const float* H_pre  = (const float*)d_in[2];
    const float* H_post = (const float*)d_in[3];
    const float* H_res  = (const float*)d_in[4];
    float* out = (float*)d_out;

    mhc_fused_kernel<<<kB, kThreads>>>(
        (const float4*)x, (const float4*)w, H_pre, H_post, H_res,
        (float4*)out);
}